// round 1
// baseline (speedup 1.0000x reference)
#include <cuda_runtime.h>
#include <cstdint>

// Problem-shape constants (guarded by runtime sizes).
#define MAX_N   100000
#define NG      256
#define DHID    64

// Scratch (allocation-free rule: __device__ globals).
__device__ float g_m[(size_t)MAX_N * DHID];      // matmul output (messages)
__device__ float g_h[(size_t)MAX_N * DHID];      // scatter accumulator / layer output
__device__ float g_pool[NG * DHID];
__device__ float g_cnt[NG];
__device__ int   g_is64;                          // 1 if indices are int64, 0 if int32

// ---------------------------------------------------------------------------
// Detect index dtype on-device: if edge_index is int64 (values < 2^31, >=0),
// every odd 32-bit word of the first 1024 elements is zero. If int32, those
// words are random node ids in [0, 100000) -> OR is nonzero w.h.p.
// ---------------------------------------------------------------------------
__global__ void detect_kernel(const unsigned int* __restrict__ w) {
    __shared__ unsigned int s;
    if (threadIdx.x == 0) s = 0u;
    __syncthreads();
    unsigned int v = 0u;
    for (int i = threadIdx.x; i < 1024; i += 256) v |= w[2 * i + 1];
    atomicOr(&s, v);
    __syncthreads();
    if (threadIdx.x == 0) g_is64 = (s == 0u) ? 1 : 0;
}

__device__ __forceinline__ int load_idx(const void* p, size_t i, int is64) {
    if (is64) return (int)(((const long long*)p)[i]);
    return ((const int*)p)[i];
}

// ---------------------------------------------------------------------------
// Zero helper (float4 granularity).
// ---------------------------------------------------------------------------
__global__ void zero_kernel(float4* __restrict__ p, int n4) {
    int t = blockIdx.x * blockDim.x + threadIdx.x;
    if (t < n4) p[t] = make_float4(0.f, 0.f, 0.f, 0.f);
}

// ---------------------------------------------------------------------------
// Dense matmul: g_m[n,64] = (RELU ? relu(A) : A)[n,K] @ W[K,64]
// Block: 256 threads, 32 rows x 64 cols per block; thread: 2 rows x 4 cols.
// W and the A-tile staged in smem. Static smem: K=128 -> 48KB, K=64 -> 24KB.
// ---------------------------------------------------------------------------
template <int K, bool RELU>
__global__ void __launch_bounds__(256) mm_kernel(const float* __restrict__ A,
                                                 const float* __restrict__ W,
                                                 int n) {
    __shared__ float  sx[32 * K];
    __shared__ float4 sw[K * 16];

    const int tid = threadIdx.x;
    const int rowbase = blockIdx.x * 32;
    constexpr int K4 = K / 4;

    // Stage W [K,64] as float4 rows of 16.
    const float4* W4 = reinterpret_cast<const float4*>(W);
    #pragma unroll
    for (int i = tid; i < K * 16; i += 256) sw[i] = W4[i];

    // Stage A tile [32,K], relu on load if requested.
    const float4* A4 = reinterpret_cast<const float4*>(A);
    #pragma unroll
    for (int i = tid; i < 32 * K4; i += 256) {
        int r = i / K4, c = i % K4;
        int gr = rowbase + r;
        float4 v = make_float4(0.f, 0.f, 0.f, 0.f);
        if (gr < n) v = A4[(size_t)gr * K4 + c];
        if (RELU) {
            v.x = fmaxf(v.x, 0.f); v.y = fmaxf(v.y, 0.f);
            v.z = fmaxf(v.z, 0.f); v.w = fmaxf(v.w, 0.f);
        }
        reinterpret_cast<float4*>(sx)[i] = v;
    }
    __syncthreads();

    const int tcol = tid & 15;        // 16 col-groups of 4
    const int trow = tid >> 4;        // 16 row-pairs
    const int r0 = trow * 2, r1 = r0 + 1;

    float4 a0 = make_float4(0.f, 0.f, 0.f, 0.f);
    float4 a1 = make_float4(0.f, 0.f, 0.f, 0.f);

    #pragma unroll 8
    for (int k = 0; k < K; k++) {
        float  x0 = sx[r0 * K + k];
        float  x1 = sx[r1 * K + k];
        float4 w  = sw[k * 16 + tcol];
        a0.x = fmaf(x0, w.x, a0.x); a0.y = fmaf(x0, w.y, a0.y);
        a0.z = fmaf(x0, w.z, a0.z); a0.w = fmaf(x0, w.w, a0.w);
        a1.x = fmaf(x1, w.x, a1.x); a1.y = fmaf(x1, w.y, a1.y);
        a1.z = fmaf(x1, w.z, a1.z); a1.w = fmaf(x1, w.w, a1.w);
    }

    int gr0 = rowbase + r0, gr1 = rowbase + r1;
    if (gr0 < n) reinterpret_cast<float4*>(g_m)[(size_t)gr0 * 16 + tcol] = a0;
    if (gr1 < n) reinterpret_cast<float4*>(g_m)[(size_t)gr1 * 16 + tcol] = a1;
}

// ---------------------------------------------------------------------------
// Scatter-add: for each edge e, g_h[dst[e]] += g_m[src[e]]  (64 floats).
// 16 threads per edge, float4 gather + red.global.add.v4.f32 (no return).
// ---------------------------------------------------------------------------
__global__ void __launch_bounds__(256) scatter_kernel(const void* __restrict__ ei, int E) {
    int t = blockIdx.x * blockDim.x + threadIdx.x;
    int e = t >> 4;
    if (e >= E) return;
    int j = t & 15;
    int is64 = g_is64;
    int s = load_idx(ei, (size_t)e, is64);
    int d = load_idx(ei, (size_t)E + e, is64);

    const float4 v = *reinterpret_cast<const float4*>(g_m + (size_t)s * 64 + j * 4);
    float* dst = g_h + (size_t)d * 64 + j * 4;
    asm volatile("red.global.add.v4.f32 [%0], {%1,%2,%3,%4};"
                 :: "l"(dst), "f"(v.x), "f"(v.y), "f"(v.z), "f"(v.w)
                 : "memory");
}

// ---------------------------------------------------------------------------
// Segment sum (pool) + counts via atomics. 16 threads per node.
// ---------------------------------------------------------------------------
__global__ void __launch_bounds__(256) pool_kernel(const void* __restrict__ batch, int n) {
    int t = blockIdx.x * blockDim.x + threadIdx.x;
    int node = t >> 4;
    if (node >= n) return;
    int j = t & 15;
    int is64 = g_is64;
    int b = load_idx(batch, (size_t)node, is64);

    const float4 v = *reinterpret_cast<const float4*>(g_h + (size_t)node * 64 + j * 4);
    float* dst = g_pool + b * 64 + j * 4;
    asm volatile("red.global.add.v4.f32 [%0], {%1,%2,%3,%4};"
                 :: "l"(dst), "f"(v.x), "f"(v.y), "f"(v.z), "f"(v.w)
                 : "memory");
    if (j == 0) atomicAdd(&g_cnt[b], 1.0f);
}

// ---------------------------------------------------------------------------
// Head: out[g,o] = (pool[g,:]/max(cnt,1)) @ Wlin[:,o]   -> [256,16]
// ---------------------------------------------------------------------------
__global__ void final_kernel(const float* __restrict__ Wlin, float* __restrict__ out) {
    int t = blockIdx.x * blockDim.x + threadIdx.x;
    if (t >= NG * 16) return;
    int g = t >> 4, o = t & 15;
    float inv = 1.0f / fmaxf(g_cnt[g], 1.0f);
    float acc = 0.f;
    #pragma unroll
    for (int k = 0; k < 64; k++)
        acc = fmaf(g_pool[g * 64 + k], Wlin[k * 16 + o], acc);
    out[t] = acc * inv;
}

// ---------------------------------------------------------------------------
extern "C" void kernel_launch(void* const* d_in, const int* in_sizes, int n_in,
                              void* d_out, int out_size) {
    const float* x    = (const float*)d_in[0];
    const float* W1   = (const float*)d_in[1];
    const float* W2   = (const float*)d_in[2];
    const float* W3   = (const float*)d_in[3];
    const float* Wlin = (const float*)d_in[4];
    const void*  ei   = d_in[5];
    const void*  bat  = d_in[6];

    const int n = in_sizes[0] / 128;   // nodes
    const int E = in_sizes[5] / 2;     // edges

    float *d_m, *d_h, *d_pool, *d_cnt;
    cudaGetSymbolAddress((void**)&d_m,    g_m);
    cudaGetSymbolAddress((void**)&d_h,    g_h);
    cudaGetSymbolAddress((void**)&d_pool, g_pool);
    cudaGetSymbolAddress((void**)&d_cnt,  g_cnt);
    (void)d_m;

    const int mm_blocks   = (n + 31) / 32;
    const int sc_blocks   = (E * 16 + 255) / 256;
    const int zero_blocks = (n * 16 + 255) / 256;   // n*64 floats / 4

    detect_kernel<<<1, 256>>>((const unsigned int*)ei);

    // Layer 1: h = scatter(x @ W1)
    zero_kernel<<<zero_blocks, 256>>>((float4*)d_h, n * 16);
    mm_kernel<128, false><<<mm_blocks, 256>>>(x, W1, n);
    scatter_kernel<<<sc_blocks, 256>>>(ei, E);

    // Layer 2: h = scatter(relu(h) @ W2)
    mm_kernel<64, true><<<mm_blocks, 256>>>(d_h, W2, n);
    zero_kernel<<<zero_blocks, 256>>>((float4*)d_h, n * 16);
    scatter_kernel<<<sc_blocks, 256>>>(ei, E);

    // Layer 3: h = scatter(relu(h) @ W3)
    mm_kernel<64, true><<<mm_blocks, 256>>>(d_h, W3, n);
    zero_kernel<<<zero_blocks, 256>>>((float4*)d_h, n * 16);
    scatter_kernel<<<sc_blocks, 256>>>(ei, E);

    // Mean pool + head
    zero_kernel<<<(NG * 16 + 255) / 256, 256>>>((float4*)d_pool, NG * 16);
    zero_kernel<<<1, 64>>>((float4*)d_cnt, NG / 4);
    pool_kernel<<<(n * 16 + 255) / 256, 256>>>(bat, n);
    final_kernel<<<16, 256>>>(Wlin, (float*)d_out);
}